// round 9
// baseline (speedup 1.0000x reference)
#include <cuda_runtime.h>
#include <cuda_fp16.h>
#include <cstdint>

// ---------------------------------------------------------------------------
// ImplicitMeshDecoder via warp-level HMMA (mma.sync m16n8k16, fp16->fp32).
//   M = 524288 rows, H = 512.  Per CTA: 128 rows, 256 threads (8 warps).
//   MT=128 halves chip-wide L2 weight traffic (4096 CTAs x 1MB = 4GB).
//   Each layer = two N=256 half-passes, warp grid 2m x 4n (warp tile 64x64).
//   The nh=0 half-output is HELD IN REGISTERS (64 x half2) until nh=1
//   finishes, so layer-1 writes A in-place with no extra SMEM buffer.
//   All 4 passes share one continuous 32-chunk cp.async weight stream
//   (32KB chunks, double-buffered); the layer-1 epilogue runs between
//   issue and wait of the next chunk, hiding its MUFU cost.
// ---------------------------------------------------------------------------

#define HDIM   512
#define MT     128
#define NT     256
#define PGRID  262144
#define BATCH  2
#define NCTA   ((BATCH * PGRID) / MT)    // 4096
#define CHUNK_HALFS 16384                // 256n * 64k
#define CHUNK_BYTES 32768

__device__ float  g_latb0[BATCH * HDIM];
__device__ __align__(16) __half g_wprep[32 * CHUNK_HALFS]; // [pass(l,nh)][kc][32KB]

// ---- helpers ---------------------------------------------------------------
static __device__ __forceinline__ uint32_t smem_u32(const void* p) {
    uint32_t a;
    asm("{ .reg .u64 t; cvta.to.shared.u64 t, %1; cvt.u32.u64 %0, t; }"
        : "=r"(a) : "l"(p));
    return a;
}
static __device__ __forceinline__ float silu(float v) {
    // exact-form silu (tanh.approx's abs error would eat the 1e-3 gate)
    return __fdividef(v, 1.0f + __expf(-v));
}
// A tile (128 x 512 fp16, 1024B rows): byte for (r, k); XOR-permute 16B cols
static __device__ __forceinline__ uint32_t a_off(int r, int k) {
    return (uint32_t)(r * 1024) + (uint32_t)((((k >> 3) ^ (r & 7)) << 4))
         + (uint32_t)((k & 7) * 2);
}
// W chunk image (256n x 64k fp16, 128B rows): byte for (n, k)
static __device__ __forceinline__ uint32_t w_off(int n, int k) {
    return (uint32_t)(n * 128) + (uint32_t)(((k >> 3) ^ (n & 7)) << 4)
         + (uint32_t)((k & 7) * 2);
}

#define LDSM4(r0, r1, r2, r3, addr)                                        \
    asm volatile("ldmatrix.sync.aligned.m8n8.x4.shared.b16 "               \
                 "{%0,%1,%2,%3}, [%4];"                                    \
                 : "=r"(r0), "=r"(r1), "=r"(r2), "=r"(r3) : "r"(addr))

#define MMA16816(d, a0, a1, a2, a3, b0, b1)                                \
    asm volatile("mma.sync.aligned.m16n8k16.row.col.f32.f16.f16.f32 "      \
                 "{%0,%1,%2,%3}, {%4,%5,%6,%7}, {%8,%9}, {%0,%1,%2,%3};"   \
                 : "+f"((d)[0]), "+f"((d)[1]), "+f"((d)[2]), "+f"((d)[3])  \
                 : "r"(a0), "r"(a1), "r"(a2), "r"(a3), "r"(b0), "r"(b1))

#define CP16(dst, src) asm volatile(                                       \
    "cp.async.cg.shared.global [%0], [%1], 16;" :: "r"(dst), "l"(src))
#define CPCOMMIT() asm volatile("cp.async.commit_group;" ::: "memory")
#define CPWAIT0()  asm volatile("cp.async.wait_group 0;" ::: "memory")

// ---- prep: latb0 = latent @ W0[:512] + b0  (one warp per output) -----------
__global__ void latb0_kernel(const float* __restrict__ lat,
                             const float* __restrict__ W0,
                             const float* __restrict__ b0) {
    int wg   = blockIdx.x * 8 + (threadIdx.x >> 5);   // 0..1023
    int lane = threadIdx.x & 31;
    int b = wg >> 9, h = wg & 511;
    const float* L = lat + b * HDIM;
    float s = 0.f;
#pragma unroll
    for (int d = lane; d < HDIM; d += 32)
        s = fmaf(L[d], W0[d * HDIM + h], s);
#pragma unroll
    for (int o = 16; o; o >>= 1) s += __shfl_xor_sync(0xffffffffu, s, o);
    if (lane == 0) g_latb0[b * HDIM + h] = s + b0[h];
}

// ---- prep: W^T + fp16 + swizzle into chunk images --------------------------
// chunk q = (l*2 + nh)*8 + kc holds WT[n = nh*256 + nn][k = kc*64 + kk]
__global__ void wprep_kernel(const float* __restrict__ W1,
                             const float* __restrict__ W2) {
    int idx = blockIdx.x * blockDim.x + threadIdx.x;   // 0 .. 2*512*512-1
    int l = idx >> 18, rem = idx & 262143;
    int k = rem >> 9, n = rem & 511;                   // source: W[k][n]
    float w = (l ? W2 : W1)[rem];
    int nh = n >> 8, nn = n & 255, kc = k >> 6, kk = k & 63;
    int chunk = (l * 2 + nh) * 8 + kc;
    g_wprep[(size_t)chunk * CHUNK_HALFS + (w_off(nn, kk) >> 1)] = __float2half_rn(w);
}

// ---- main fused kernel -----------------------------------------------------
__global__ __launch_bounds__(NT, 1)
void mlp_hmma_kernel(const float* __restrict__ W0,
                     const float* __restrict__ b1,
                     const float* __restrict__ b2,
                     const float* __restrict__ W3,
                     const float* __restrict__ b3,
                     float* __restrict__ out) {
    extern __shared__ char dyn[];
    uint32_t sbase = smem_u32(dyn);
    uint32_t s0 = (sbase + 1023u) & ~1023u;
    char* base = dyn + (s0 - sbase);

    char*  sA    = base;                       // 131072 (in-place across layers)
    float* sW3   = (float*)(base + 196608);    // 2048
    float* sB1   = (float*)(base + 198656);    // 2048
    float* sB2   = (float*)(base + 200704);    // 2048
    float* spart = (float*)(base + 202752);    // 2048 (128 rows x 4 wn)
    float* sb3   = (float*)(base + 204800);
    const uint32_t u_A = s0;
    const uint32_t u_W[2] = { s0 + 131072, s0 + 131072 + CHUNK_BYTES };

    const int tid  = threadIdx.x;
    const int lane = tid & 31, wid = tid >> 5;
    const int wm   = wid >> 2;                 // 0..1 : rows wm*64
    const int wn   = wid & 3;                  // 0..3 : cols (nh*256 +) wn*64
    const int m0   = blockIdx.x * MT;

    sW3[tid] = W3[tid];  sW3[tid + 256] = W3[tid + 256];
    sB1[tid] = b1[tid];  sB1[tid + 256] = b1[tid + 256];
    sB2[tid] = b2[tid];  sB2[tid + 256] = b2[tid + 256];
    if (tid == 0) *sb3 = b3[0];

    // -------- layer 0: analytic coords + latent -> silu -> A --------
    {
        const float* Wc = W0 + (size_t)HDIM * HDIM;
        const int b = m0 >> 18;
        const int n = tid * 2;                 // 256 threads x col-pair
        float la0 = g_latb0[b * HDIM + n],     la1 = g_latb0[b * HDIM + n + 1];
        float c00 = Wc[n],            c01 = Wc[n + 1];
        float c10 = Wc[HDIM + n],     c11 = Wc[HDIM + n + 1];
        float c20 = Wc[2 * HDIM + n], c21 = Wc[2 * HDIM + n + 1];
#pragma unroll 4
        for (int r = 0; r < MT; r++) {
            int p = (m0 + r) & (PGRID - 1);
            float x = -1.2f + (float)(p >> 12)       * (2.4f / 63.0f);
            float y = -1.2f + (float)((p >> 6) & 63) * (2.4f / 63.0f);
            float z = -1.2f + (float)(p & 63)        * (2.4f / 63.0f);
            float v0 = silu(fmaf(x, c00, fmaf(y, c10, fmaf(z, c20, la0))));
            float v1 = silu(fmaf(x, c01, fmaf(y, c11, fmaf(z, c21, la1))));
            *(__half2*)(sA + a_off(r, n)) = __floats2half2_rn(v0, v1);
        }
    }

    // per-lane ldmatrix addressing (invariant across all passes)
    const int x7 = lane & 7;                   // XOR term (== row&7 everywhere)
    const int ka = lane >> 4;                  // A k8-offset
    const int kb = (lane >> 3) & 1;            // B k8-offset
    uint32_t aR[4], bR[4];
#pragma unroll
    for (int i = 0; i < 4; i++)
        aR[i] = (uint32_t)((wm * 64 + i * 16 + (lane & 15)) * 1024);
#pragma unroll
    for (int j = 0; j < 4; j++)
        bR[j] = (uint32_t)((wn * 64 + j * 16 + x7 + ((lane >> 4) << 3)) * 128);

    float   acc[4][8][4];                      // 64m x 64n per warp
    __half2 h2out[4][8][2];                    // held nh=0 layer-1 output
    float   pr[4][2];                          // layer-2 row partials
#pragma unroll
    for (int mg = 0; mg < 4; mg++) {
        pr[mg][0] = 0.f; pr[mg][1] = 0.f;
#pragma unroll
        for (int ng = 0; ng < 8; ng++)
#pragma unroll
            for (int i = 0; i < 4; i++) acc[mg][ng][i] = 0.f;
    }

    // prologue: stage chunk 0
    {
        const char* g = (const char*)g_wprep + tid * 16;
        uint32_t d = u_W[0] + (uint32_t)tid * 16;
#pragma unroll
        for (int i = 0; i < 8; i++) CP16(d + i * 4096, g + i * 4096);
        CPCOMMIT(); CPWAIT0();
    }
    __syncthreads();   // also orders layer-0 A writes

    // ---- continuous 32-chunk stream: q = (l*2 + nh)*8 + c ----
#pragma unroll 1
    for (int q = 0; q < 32; q++) {
        const int c = q & 7;
        if (q < 31) {   // stage chunk q+1 (overlaps MMA body below)
            const char* g = (const char*)g_wprep
                          + (size_t)(q + 1) * CHUNK_BYTES + tid * 16;
            uint32_t d = u_W[(q + 1) & 1] + (uint32_t)tid * 16;
#pragma unroll
            for (int i = 0; i < 8; i++) CP16(d + i * 4096, g + i * 4096);
            CPCOMMIT();
        }
        const uint32_t wb = u_W[q & 1];
#pragma unroll
        for (int ks = 0; ks < 4; ks++) {
            const int kbA = c * 8 + ks * 2 + ka;      // global k>>3
            const int kbB = ks * 2 + kb;              // chunk-local k>>3
            uint32_t ar[4][4], br[4][4];
#pragma unroll
            for (int i = 0; i < 4; i++)
                LDSM4(ar[i][0], ar[i][1], ar[i][2], ar[i][3],
                      u_A + aR[i] + (uint32_t)((kbA ^ x7) << 4));
#pragma unroll
            for (int j = 0; j < 4; j++)
                LDSM4(br[j][0], br[j][1], br[j][2], br[j][3],
                      wb + bR[j] + (uint32_t)((kbB ^ x7) << 4));
#pragma unroll
            for (int mg = 0; mg < 4; mg++)
#pragma unroll
                for (int j = 0; j < 4; j++) {
                    MMA16816(acc[mg][2 * j],     ar[mg][0], ar[mg][1],
                             ar[mg][2], ar[mg][3], br[j][0], br[j][1]);
                    MMA16816(acc[mg][2 * j + 1], ar[mg][0], ar[mg][1],
                             ar[mg][2], ar[mg][3], br[j][2], br[j][3]);
                }
        }

        if (q == 15) {
            // layer-1 complete.  Sync (A reads done), then write BOTH halves
            // in-place while chunk 16's cp.async is still in flight.
            __syncthreads();
#pragma unroll
            for (int mg = 0; mg < 4; mg++) {
                int rbase = wm * 64 + mg * 16 + (lane >> 2);
#pragma unroll
                for (int ng = 0; ng < 8; ng++) {
                    int nc = wn * 64 + ng * 8 + 2 * (lane & 3);
                    // held nh=0 half (cols nc)
                    *(__half2*)(sA + a_off(rbase,     nc)) = h2out[mg][ng][0];
                    *(__half2*)(sA + a_off(rbase + 8, nc)) = h2out[mg][ng][1];
                    // fresh nh=1 half (cols 256 + nc)
                    float bb0 = sB1[256 + nc], bb1 = sB1[256 + nc + 1];
                    float v0 = silu(acc[mg][ng][0] + bb0);
                    float v1 = silu(acc[mg][ng][1] + bb1);
                    *(__half2*)(sA + a_off(rbase, 256 + nc))
                        = __floats2half2_rn(v0, v1);
                    v0 = silu(acc[mg][ng][2] + bb0);
                    v1 = silu(acc[mg][ng][3] + bb1);
                    *(__half2*)(sA + a_off(rbase + 8, 256 + nc))
                        = __floats2half2_rn(v0, v1);
                }
            }
        }

        CPWAIT0();
        __syncthreads();

        // ---- pass-boundary register ops ----
        if (q == 7) {
            // hold nh=0 layer-1 output in registers (bias + silu + fp16)
#pragma unroll
            for (int mg = 0; mg < 4; mg++)
#pragma unroll
                for (int ng = 0; ng < 8; ng++) {
                    int nc = wn * 64 + ng * 8 + 2 * (lane & 3);
                    float bb0 = sB1[nc], bb1 = sB1[nc + 1];
                    h2out[mg][ng][0] = __floats2half2_rn(
                        silu(acc[mg][ng][0] + bb0), silu(acc[mg][ng][1] + bb1));
                    h2out[mg][ng][1] = __floats2half2_rn(
                        silu(acc[mg][ng][2] + bb0), silu(acc[mg][ng][3] + bb1));
                    acc[mg][ng][0] = 0.f; acc[mg][ng][1] = 0.f;
                    acc[mg][ng][2] = 0.f; acc[mg][ng][3] = 0.f;
                }
        } else if (q == 15) {
#pragma unroll
            for (int mg = 0; mg < 4; mg++)
#pragma unroll
                for (int ng = 0; ng < 8; ng++)
#pragma unroll
                    for (int i = 0; i < 4; i++) acc[mg][ng][i] = 0.f;
        } else if (q == 23 || q == 31) {
            // layer-2 half done: bias + silu + W3 dot folded into partials
            const int nb = (q == 23) ? 0 : 256;
#pragma unroll
            for (int mg = 0; mg < 4; mg++)
#pragma unroll
                for (int ng = 0; ng < 8; ng++) {
                    int nc = nb + wn * 64 + ng * 8 + 2 * (lane & 3);
                    float bb0 = sB2[nc], bb1 = sB2[nc + 1];
                    float w0 = sW3[nc],  w1 = sW3[nc + 1];
                    pr[mg][0] = fmaf(silu(acc[mg][ng][0] + bb0), w0, pr[mg][0]);
                    pr[mg][0] = fmaf(silu(acc[mg][ng][1] + bb1), w1, pr[mg][0]);
                    pr[mg][1] = fmaf(silu(acc[mg][ng][2] + bb0), w0, pr[mg][1]);
                    pr[mg][1] = fmaf(silu(acc[mg][ng][3] + bb1), w1, pr[mg][1]);
                    if (q == 23) {
                        acc[mg][ng][0] = 0.f; acc[mg][ng][1] = 0.f;
                        acc[mg][ng][2] = 0.f; acc[mg][ng][3] = 0.f;
                    }
                }
        }
    }

    // -------- final reduction: lanes (cols) -> warps (wn) -> rows --------
#pragma unroll
    for (int mg = 0; mg < 4; mg++)
#pragma unroll
        for (int h = 0; h < 2; h++) {
            float v = pr[mg][h];
            v += __shfl_xor_sync(0xffffffffu, v, 1);
            v += __shfl_xor_sync(0xffffffffu, v, 2);
            if ((lane & 3) == 0) {
                int r = wm * 64 + mg * 16 + (lane >> 2) + 8 * h;
                spart[r * 4 + wn] = v;
            }
        }
    __syncthreads();
    if (tid < MT) {
        float s = *sb3;
#pragma unroll
        for (int w = 0; w < 4; w++) s += spart[tid * 4 + w];
        out[m0 + tid] = s;
    }
}

// ---------------------------------------------------------------------------
extern "C" void kernel_launch(void* const* d_in, const int* in_sizes, int n_in,
                              void* d_out, int out_size) {
    const float* lat = (const float*)d_in[0];
    const float* W0  = (const float*)d_in[1];
    const float* b0  = (const float*)d_in[2];
    const float* W1  = (const float*)d_in[3];
    const float* b1  = (const float*)d_in[4];
    const float* W2  = (const float*)d_in[5];
    const float* b2  = (const float*)d_in[6];
    const float* W3  = (const float*)d_in[7];
    const float* b3  = (const float*)d_in[8];
    float* out = (float*)d_out;

    latb0_kernel<<<128, 256>>>(lat, W0, b0);
    wprep_kernel<<<1024, 512>>>(W1, W2);

    size_t smem = 1024 + 204800 + 64;   // slack + A(128K) + 2x32K W + scalars
    cudaFuncSetAttribute(mlp_hmma_kernel,
                         cudaFuncAttributeMaxDynamicSharedMemorySize, (int)smem);
    mlp_hmma_kernel<<<NCTA, NT, smem>>>(W0, b1, b2, W3, b3, out);
}

// round 10
// speedup vs baseline: 1.1119x; 1.1119x over previous
#include <cuda_runtime.h>
#include <cuda_fp16.h>
#include <cstdint>

// ---------------------------------------------------------------------------
// ImplicitMeshDecoder via warp-level HMMA (mma.sync m16n8k16, fp16->fp32).
//   M = 524288 rows, H = 512.  Per CTA: 64 rows, 256 threads (8 warps).
//   Full-width N=512 sweep per layer, warp grid 1m x 8n (warp tile 64x64).
//   NEW (R10): B never touches SMEM.  wprep emits mma.sync B-fragment words
//   directly; each warp LDG.128s its fragments to registers (L2-broadcast
//   across all CTAs).  Kills W STS + B LDSM crossbar traffic, all per-chunk
//   barriers, and cp.async bubbles.  A stays in one 64KB SMEM tile, in-place.
//   layer0 : analytic coords + latent  -> silu -> A (SMEM fp16, XOR-swz)
//   layer1 : A @ W1 + b1  (HMMA)       -> silu -> A (in-place)
//   layer2 : A @ W2 + b2  (HMMA)       -> silu -> dot W3 (reg-folded) -> out
// ---------------------------------------------------------------------------

#define HDIM   512
#define MT     64
#define NT     256
#define PGRID  262144
#define BATCH  2
#define NCTA   ((BATCH * PGRID) / MT)    // 8192

// B fragment store: word (l, k16, wn, v, lane, e):
//   ng = 2v + (e>>1), half = e&1
//   n  = wn*64 + ng*8 + (lane>>2)
//   k0 = k16*16 + (lane&3)*2 + half*8
//   word = half2( W[k0][n], W[k0+1][n] )
// uint4 index: ((k16*8 + wn)*4 + v)*32 + lane   (per layer 32768 uint4 = 512KB)
__device__ float g_latb0[BATCH * HDIM];
__device__ __align__(16) uint4 g_wfrag[2 * 32768];

// ---- helpers ---------------------------------------------------------------
static __device__ __forceinline__ uint32_t smem_u32(const void* p) {
    uint32_t a;
    asm("{ .reg .u64 t; cvta.to.shared.u64 t, %1; cvt.u32.u64 %0, t; }"
        : "=r"(a) : "l"(p));
    return a;
}
static __device__ __forceinline__ float silu(float v) {
    // exact-form silu (tanh.approx's abs error would eat the 1e-3 gate)
    return __fdividef(v, 1.0f + __expf(-v));
}
// A tile (64 x 512 fp16, 1024B rows): byte for (r, k); XOR-permute 16B cols
static __device__ __forceinline__ uint32_t a_off(int r, int k) {
    return (uint32_t)(r * 1024) + (uint32_t)((((k >> 3) ^ (r & 7)) << 4))
         + (uint32_t)((k & 7) * 2);
}

#define LDSM4(r0, r1, r2, r3, addr)                                        \
    asm volatile("ldmatrix.sync.aligned.m8n8.x4.shared.b16 "               \
                 "{%0,%1,%2,%3}, [%4];"                                    \
                 : "=r"(r0), "=r"(r1), "=r"(r2), "=r"(r3) : "r"(addr))

#define MMA16816(d, a0, a1, a2, a3, b0, b1)                                \
    asm volatile("mma.sync.aligned.m16n8k16.row.col.f32.f16.f16.f32 "      \
                 "{%0,%1,%2,%3}, {%4,%5,%6,%7}, {%8,%9}, {%0,%1,%2,%3};"   \
                 : "+f"((d)[0]), "+f"((d)[1]), "+f"((d)[2]), "+f"((d)[3])  \
                 : "r"(a0), "r"(a1), "r"(a2), "r"(a3), "r"(b0), "r"(b1))

// ---- prep: latb0 = latent @ W0[:512] + b0  (one warp per output) -----------
__global__ void latb0_kernel(const float* __restrict__ lat,
                             const float* __restrict__ W0,
                             const float* __restrict__ b0) {
    int wg   = blockIdx.x * 8 + (threadIdx.x >> 5);   // 0..1023
    int lane = threadIdx.x & 31;
    int b = wg >> 9, h = wg & 511;
    const float* L = lat + b * HDIM;
    float s = 0.f;
#pragma unroll
    for (int d = lane; d < HDIM; d += 32)
        s = fmaf(L[d], W0[d * HDIM + h], s);
#pragma unroll
    for (int o = 16; o; o >>= 1) s += __shfl_xor_sync(0xffffffffu, s, o);
    if (lane == 0) g_latb0[b * HDIM + h] = s + b0[h];
}

// ---- prep: W1/W2 -> fp16 mma.sync B-fragment words -------------------------
// One thread per 4B word (262144 threads total).
__global__ void wprep_kernel(const float* __restrict__ W1,
                             const float* __restrict__ W2) {
    int idx  = blockIdx.x * blockDim.x + threadIdx.x;   // 0 .. 262143
    int e    = idx & 3;
    int lane = (idx >> 2) & 31;
    int v    = (idx >> 7) & 3;
    int wn   = (idx >> 9) & 7;
    int k16  = (idx >> 12) & 31;
    int l    = (idx >> 17) & 1;
    int ng   = 2 * v + (e >> 1);
    int half = e & 1;
    int n  = wn * 64 + ng * 8 + (lane >> 2);
    int k0 = k16 * 16 + (lane & 3) * 2 + half * 8;
    const float* W = l ? W2 : W1;
    __half2 w = __floats2half2_rn(W[k0 * HDIM + n], W[(k0 + 1) * HDIM + n]);
    ((__half2*)g_wfrag)[idx] = w;
}

// ---- main fused kernel -----------------------------------------------------
__global__ __launch_bounds__(NT, 1)
void mlp_hmma_kernel(const float* __restrict__ W0,
                     const float* __restrict__ b1,
                     const float* __restrict__ b2,
                     const float* __restrict__ W3,
                     const float* __restrict__ b3,
                     float* __restrict__ out) {
    extern __shared__ char dyn[];
    uint32_t sbase = smem_u32(dyn);
    uint32_t s0 = (sbase + 1023u) & ~1023u;
    char* base = dyn + (s0 - sbase);

    char*  sA    = base;                       // 65536 (in-place across layers)
    float* sW3   = (float*)(base + 65536);     // 2048
    float* sB1   = (float*)(base + 67584);     // 2048
    float* sB2   = (float*)(base + 69632);     // 2048
    float* spart = (float*)(base + 71680);     // 2048 (64 rows x 8 warps)
    float* sb3   = (float*)(base + 73728);
    const uint32_t u_A = s0;

    const int tid  = threadIdx.x;
    const int lane = tid & 31, wid = tid >> 5;   // wid = n-group (cols wid*64)
    const int m0   = blockIdx.x * MT;

    sW3[tid] = W3[tid];  sW3[tid + 256] = W3[tid + 256];
    sB1[tid] = b1[tid];  sB1[tid + 256] = b1[tid + 256];
    sB2[tid] = b2[tid];  sB2[tid + 256] = b2[tid + 256];
    if (tid == 0) *sb3 = b3[0];

    // -------- layer 0: analytic coords + latent -> silu -> A --------
    {
        const float* Wc = W0 + (size_t)HDIM * HDIM;
        const int b = m0 >> 18;
        const int n = tid * 2;                 // 256 threads x col-pair
        float la0 = g_latb0[b * HDIM + n],     la1 = g_latb0[b * HDIM + n + 1];
        float c00 = Wc[n],            c01 = Wc[n + 1];
        float c10 = Wc[HDIM + n],     c11 = Wc[HDIM + n + 1];
        float c20 = Wc[2 * HDIM + n], c21 = Wc[2 * HDIM + n + 1];
#pragma unroll 4
        for (int r = 0; r < MT; r++) {
            int p = (m0 + r) & (PGRID - 1);
            float x = -1.2f + (float)(p >> 12)       * (2.4f / 63.0f);
            float y = -1.2f + (float)((p >> 6) & 63) * (2.4f / 63.0f);
            float z = -1.2f + (float)(p & 63)        * (2.4f / 63.0f);
            float v0 = silu(fmaf(x, c00, fmaf(y, c10, fmaf(z, c20, la0))));
            float v1 = silu(fmaf(x, c01, fmaf(y, c11, fmaf(z, c21, la1))));
            *(__half2*)(sA + a_off(r, n)) = __floats2half2_rn(v0, v1);
        }
    }
    __syncthreads();

    // per-lane A ldmatrix addressing (invariant across layers)
    const int x7 = lane & 7;                   // XOR term (== row&7 everywhere)
    const int ka = lane >> 4;                  // A k8-offset
    uint32_t aR[4];
#pragma unroll
    for (int i = 0; i < 4; i++)
        aR[i] = (uint32_t)((i * 16 + (lane & 15)) * 1024);

    float pr[4][2];                            // layer-2 row partials
#pragma unroll
    for (int mg = 0; mg < 4; mg++) { pr[mg][0] = 0.f; pr[mg][1] = 0.f; }

#pragma unroll 1
    for (int l = 0; l < 2; l++) {
        // per-warp B fragment stream for this layer
        const uint4* wf = g_wfrag + (size_t)l * 32768
                        + (size_t)(wid * 4) * 32 + lane;   // k16=0, v=0

        float acc[4][8][4];                    // 64m x 64n per warp
#pragma unroll
        for (int mg = 0; mg < 4; mg++)
#pragma unroll
            for (int ng = 0; ng < 8; ng++)
#pragma unroll
                for (int i = 0; i < 4; i++) acc[mg][ng][i] = 0.f;

        uint4 bc[4], bn[4];
#pragma unroll
        for (int v = 0; v < 4; v++)            // preload k16 = 0
            bc[v] = __ldg(wf + v * 32);

#pragma unroll 2
        for (int k16 = 0; k16 < 32; k16++) {
            if (k16 < 31) {                    // prefetch next k16's fragments
                const uint4* p = wf + (size_t)(k16 + 1) * 1024;  // 8*4*32
#pragma unroll
                for (int v = 0; v < 4; v++) bn[v] = __ldg(p + v * 32);
            }
            const int kbA = k16 * 2 + ka;      // A k8-block index
            uint32_t ar[4][4];
#pragma unroll
            for (int i = 0; i < 4; i++)
                LDSM4(ar[i][0], ar[i][1], ar[i][2], ar[i][3],
                      u_A + aR[i] + (uint32_t)((kbA ^ x7) << 4));
#pragma unroll
            for (int mg = 0; mg < 4; mg++)
#pragma unroll
                for (int v = 0; v < 4; v++) {
                    MMA16816(acc[mg][2 * v],     ar[mg][0], ar[mg][1],
                             ar[mg][2], ar[mg][3], bc[v].x, bc[v].y);
                    MMA16816(acc[mg][2 * v + 1], ar[mg][0], ar[mg][1],
                             ar[mg][2], ar[mg][3], bc[v].z, bc[v].w);
                }
#pragma unroll
            for (int v = 0; v < 4; v++) bc[v] = bn[v];
        }

        // -------- epilogue (adds layer bias, then silu) --------
        if (l == 0) {
            __syncthreads();   // all warps done reading A -> safe to overwrite
#pragma unroll
            for (int mg = 0; mg < 4; mg++) {
                int rbase = mg * 16 + (lane >> 2);
#pragma unroll
                for (int ng = 0; ng < 8; ng++) {
                    int nc = wid * 64 + ng * 8 + 2 * (lane & 3);
                    float bb0 = sB1[nc], bb1 = sB1[nc + 1];
                    float v0 = silu(acc[mg][ng][0] + bb0);
                    float v1 = silu(acc[mg][ng][1] + bb1);
                    *(__half2*)(sA + a_off(rbase, nc)) = __floats2half2_rn(v0, v1);
                    v0 = silu(acc[mg][ng][2] + bb0);
                    v1 = silu(acc[mg][ng][3] + bb1);
                    *(__half2*)(sA + a_off(rbase + 8, nc)) = __floats2half2_rn(v0, v1);
                }
            }
            __syncthreads();   // A rewritten -> visible to layer-2 reads
        } else {
            // bias + silu + W3 dot folded into row partials
#pragma unroll
            for (int mg = 0; mg < 4; mg++)
#pragma unroll
                for (int ng = 0; ng < 8; ng++) {
                    int nc = wid * 64 + ng * 8 + 2 * (lane & 3);
                    float bb0 = sB2[nc], bb1 = sB2[nc + 1];
                    float w0 = sW3[nc],  w1 = sW3[nc + 1];
                    pr[mg][0] = fmaf(silu(acc[mg][ng][0] + bb0), w0, pr[mg][0]);
                    pr[mg][0] = fmaf(silu(acc[mg][ng][1] + bb1), w1, pr[mg][0]);
                    pr[mg][1] = fmaf(silu(acc[mg][ng][2] + bb0), w0, pr[mg][1]);
                    pr[mg][1] = fmaf(silu(acc[mg][ng][3] + bb1), w1, pr[mg][1]);
                }
        }
    }

    // -------- final reduction: lanes (cols) -> warps -> rows --------
#pragma unroll
    for (int mg = 0; mg < 4; mg++)
#pragma unroll
        for (int h = 0; h < 2; h++) {
            float v = pr[mg][h];
            v += __shfl_xor_sync(0xffffffffu, v, 1);
            v += __shfl_xor_sync(0xffffffffu, v, 2);
            if ((lane & 3) == 0) {
                int r = mg * 16 + (lane >> 2) + 8 * h;
                spart[r * 8 + wid] = v;
            }
        }
    __syncthreads();
    if (tid < MT) {
        float s = *sb3;
#pragma unroll
        for (int w = 0; w < 8; w++) s += spart[tid * 8 + w];
        out[m0 + tid] = s;
    }
}

// ---------------------------------------------------------------------------
extern "C" void kernel_launch(void* const* d_in, const int* in_sizes, int n_in,
                              void* d_out, int out_size) {
    const float* lat = (const float*)d_in[0];
    const float* W0  = (const float*)d_in[1];
    const float* b0  = (const float*)d_in[2];
    const float* W1  = (const float*)d_in[3];
    const float* b1  = (const float*)d_in[4];
    const float* W2  = (const float*)d_in[5];
    const float* b2  = (const float*)d_in[6];
    const float* W3  = (const float*)d_in[7];
    const float* b3  = (const float*)d_in[8];
    float* out = (float*)d_out;

    latb0_kernel<<<128, 256>>>(lat, W0, b0);
    wprep_kernel<<<512, 512>>>(W1, W2);

    size_t smem = 1024 + 73728 + 64;   // slack + A(64K) + scalars
    cudaFuncSetAttribute(mlp_hmma_kernel,
                         cudaFuncAttributeMaxDynamicSharedMemorySize, (int)smem);
    mlp_hmma_kernel<<<NCTA, NT, smem>>>(W0, b1, b2, W3, b3, out);
}